// round 9
// baseline (speedup 1.0000x reference)
#include <cuda_runtime.h>
#include <math.h>

// Problem constants
#define BB 256   // batch == N (broadcast requirement)
#define NN 256   // feature vectors per sample
#define DD 1024  // feature dim
#define SS 1024  // state dim

// ----- device scratch (allocation-free rule: __device__ globals) -----
__device__ __align__(16) float g_A[BB * SS];        // A = state @ Q^T   [256,1024]
__device__ __align__(16) float g_M[BB * NN];        // M = A @ K         [256,256]
__device__ __align__(16) float g_rowmax[BB * BB];   // per (i,b) row max
__device__ __align__(16) float g_rowinv[BB * BB];   // per (i,b) 1/sumexp

// ============================================================================
// P1a: A[b,s] = sum_k state[b,k] * Q[s,k]   (GEMM NT, C=[256,1024], K=1024)
// 64x64 tile, TK=16, 256 threads, 4x4 microtile.
// ============================================================================
__global__ __launch_bounds__(256) void gemm_state_qt(
    const float* __restrict__ state, const float* __restrict__ Q)
{
    __shared__ __align__(16) float As[16][64];
    __shared__ __align__(16) float Bs[16][64];
    const int tid   = threadIdx.x;
    const int sBase = blockIdx.x * 64;
    const int bBase = blockIdx.y * 64;
    const int tx = tid & 15, ty = tid >> 4;
    const int r   = tid >> 2;          // 0..63
    const int kk4 = (tid & 3) * 4;     // 0,4,8,12

    float acc[4][4] = {};

    for (int k0 = 0; k0 < SS; k0 += 16) {
        float4 va = *(const float4*)&state[(size_t)(bBase + r) * SS + k0 + kk4];
        float4 vb = *(const float4*)&Q[(size_t)(sBase + r) * SS + k0 + kk4];
        __syncthreads();
        As[kk4 + 0][r] = va.x; As[kk4 + 1][r] = va.y;
        As[kk4 + 2][r] = va.z; As[kk4 + 3][r] = va.w;
        Bs[kk4 + 0][r] = vb.x; Bs[kk4 + 1][r] = vb.y;
        Bs[kk4 + 2][r] = vb.z; Bs[kk4 + 3][r] = vb.w;
        __syncthreads();
        #pragma unroll
        for (int kk = 0; kk < 16; ++kk) {
            float4 a4 = *(const float4*)&As[kk][ty * 4];
            float4 b4 = *(const float4*)&Bs[kk][tx * 4];
            float a[4] = {a4.x, a4.y, a4.z, a4.w};
            float b[4] = {b4.x, b4.y, b4.z, b4.w};
            #pragma unroll
            for (int x = 0; x < 4; ++x)
                #pragma unroll
                for (int y = 0; y < 4; ++y)
                    acc[x][y] = fmaf(a[x], b[y], acc[x][y]);
        }
    }
    #pragma unroll
    for (int x = 0; x < 4; ++x) {
        float4 o = {acc[x][0], acc[x][1], acc[x][2], acc[x][3]};
        *(float4*)&g_A[(size_t)(bBase + ty * 4 + x) * SS + sBase + tx * 4] = o;
    }
}

// ============================================================================
// P1b: M[b,n] = sum_s A[b,s] * K[s,n]   (GEMM NN, C=[256,256], K=1024)
// ============================================================================
__global__ __launch_bounds__(256) void gemm_a_k(const float* __restrict__ Kmat)
{
    __shared__ __align__(16) float As[16][64];
    __shared__ __align__(16) float Bs[16][64];
    const int tid   = threadIdx.x;
    const int nBase = blockIdx.x * 64;
    const int bBase = blockIdx.y * 64;
    const int tx = tid & 15, ty = tid >> 4;
    const int r   = tid >> 2;
    const int kk4 = (tid & 3) * 4;
    const int kkb = tid >> 4;          // 0..15
    const int nn4 = (tid & 15) * 4;    // 0..60

    float acc[4][4] = {};

    for (int k0 = 0; k0 < SS; k0 += 16) {
        float4 va = *(const float4*)&g_A[(size_t)(bBase + r) * SS + k0 + kk4];
        float4 vb = *(const float4*)&Kmat[(size_t)(k0 + kkb) * NN + nBase + nn4];
        __syncthreads();
        As[kk4 + 0][r] = va.x; As[kk4 + 1][r] = va.y;
        As[kk4 + 2][r] = va.z; As[kk4 + 3][r] = va.w;
        *(float4*)&Bs[kkb][nn4] = vb;
        __syncthreads();
        #pragma unroll
        for (int kk = 0; kk < 16; ++kk) {
            float4 a4 = *(const float4*)&As[kk][ty * 4];
            float4 b4 = *(const float4*)&Bs[kk][tx * 4];
            float a[4] = {a4.x, a4.y, a4.z, a4.w};
            float b[4] = {b4.x, b4.y, b4.z, b4.w};
            #pragma unroll
            for (int x = 0; x < 4; ++x)
                #pragma unroll
                for (int y = 0; y < 4; ++y)
                    acc[x][y] = fmaf(a[x], b[y], acc[x][y]);
        }
    }
    #pragma unroll
    for (int x = 0; x < 4; ++x) {
        float4 o = {acc[x][0], acc[x][1], acc[x][2], acc[x][3]};
        *(float4*)&g_M[(size_t)(bBase + ty * 4 + x) * NN + nBase + tx * 4] = o;
    }
}

// ============================================================================
// P2: batched logits GEMM.  L[i,b,d] = sum_n M[b,n] * FV[i,n,d]
// per-i GEMM [256x1024, K=256]. 128x128 tile, TK=16, 256 threads, 8x8 micro,
// double-buffered SMEM with register prefetch. This is the dominant cost
// (17.2 G-MAC fp32).
// ============================================================================
__global__ __launch_bounds__(256, 2) void logits_kernel(
    const float* __restrict__ FV, float* __restrict__ L)
{
    __shared__ __align__(16) float As[2][16][128];  // M^T tile  [k][b]
    __shared__ __align__(16) float Bs[2][16][128];  // FV tile   [k][d]

    const int dBase = blockIdx.x * 128;
    const int bBase = blockIdx.y * 128;
    const int i     = blockIdx.z;
    const int tid   = threadIdx.x;
    const int tx = tid & 15, ty = tid >> 4;

    // loader indexing (512 float4 per tile, 2 per thread)
    const int ar0  = tid >> 2;           // 0..63 (+64 for second)
    const int akk  = (tid & 3) * 4;      // 0,4,8,12
    const int bkk0 = tid >> 5;           // 0..7 (+8 for second)
    const int bdd  = (tid & 31) * 4;     // 0..124

    const float* FVi = FV + (size_t)i * NN * DD;

    float4 a0, a1, b0, b1;
    float acc[8][8] = {};

    // prologue: chunk 0
    {
        const int k0 = 0;
        a0 = *(const float4*)&g_M[(size_t)(bBase + ar0)      * NN + k0 + akk];
        a1 = *(const float4*)&g_M[(size_t)(bBase + ar0 + 64) * NN + k0 + akk];
        b0 = *(const float4*)&FVi[(size_t)(k0 + bkk0)     * DD + dBase + bdd];
        b1 = *(const float4*)&FVi[(size_t)(k0 + bkk0 + 8) * DD + dBase + bdd];
        As[0][akk + 0][ar0] = a0.x; As[0][akk + 1][ar0] = a0.y;
        As[0][akk + 2][ar0] = a0.z; As[0][akk + 3][ar0] = a0.w;
        As[0][akk + 0][ar0 + 64] = a1.x; As[0][akk + 1][ar0 + 64] = a1.y;
        As[0][akk + 2][ar0 + 64] = a1.z; As[0][akk + 3][ar0 + 64] = a1.w;
        *(float4*)&Bs[0][bkk0][bdd]     = b0;
        *(float4*)&Bs[0][bkk0 + 8][bdd] = b1;
    }
    __syncthreads();

    int buf = 0;
    for (int c = 0; c < 16; ++c) {
        if (c + 1 < 16) {
            const int k0 = (c + 1) * 16;
            a0 = *(const float4*)&g_M[(size_t)(bBase + ar0)      * NN + k0 + akk];
            a1 = *(const float4*)&g_M[(size_t)(bBase + ar0 + 64) * NN + k0 + akk];
            b0 = *(const float4*)&FVi[(size_t)(k0 + bkk0)     * DD + dBase + bdd];
            b1 = *(const float4*)&FVi[(size_t)(k0 + bkk0 + 8) * DD + dBase + bdd];
        }
        #pragma unroll
        for (int kk = 0; kk < 16; ++kk) {
            float a[8], b[8];
            *(float4*)&a[0] = *(const float4*)&As[buf][kk][ty * 8];
            *(float4*)&a[4] = *(const float4*)&As[buf][kk][ty * 8 + 4];
            *(float4*)&b[0] = *(const float4*)&Bs[buf][kk][tx * 8];
            *(float4*)&b[4] = *(const float4*)&Bs[buf][kk][tx * 8 + 4];
            #pragma unroll
            for (int x = 0; x < 8; ++x)
                #pragma unroll
                for (int y = 0; y < 8; ++y)
                    acc[x][y] = fmaf(a[x], b[y], acc[x][y]);
        }
        if (c + 1 < 16) {
            __syncthreads();
            const int nb = buf ^ 1;
            As[nb][akk + 0][ar0] = a0.x; As[nb][akk + 1][ar0] = a0.y;
            As[nb][akk + 2][ar0] = a0.z; As[nb][akk + 3][ar0] = a0.w;
            As[nb][akk + 0][ar0 + 64] = a1.x; As[nb][akk + 1][ar0 + 64] = a1.y;
            As[nb][akk + 2][ar0 + 64] = a1.z; As[nb][akk + 3][ar0 + 64] = a1.w;
            *(float4*)&Bs[nb][bkk0][bdd]     = b0;
            *(float4*)&Bs[nb][bkk0 + 8][bdd] = b1;
            __syncthreads();
            buf = nb;
        }
    }

    // epilogue: write logits into the W output region (used as scratch)
    const size_t base = ((size_t)i * BB + bBase + ty * 8) * DD + dBase + tx * 8;
    #pragma unroll
    for (int x = 0; x < 8; ++x) {
        float4 o0 = {acc[x][0], acc[x][1], acc[x][2], acc[x][3]};
        float4 o1 = {acc[x][4], acc[x][5], acc[x][6], acc[x][7]};
        *(float4*)&L[base + (size_t)x * DD]     = o0;
        *(float4*)&L[base + (size_t)x * DD + 4] = o1;
    }
}

// ============================================================================
// P3: per-row (i,b) softmax stats over d: rowmax and 1/sum(exp).
// One warp per 1024-float row; row cached in registers (8 float4/lane).
// ============================================================================
__global__ __launch_bounds__(256) void stats_kernel(const float* __restrict__ L)
{
    const int warp = threadIdx.x >> 5;
    const int lane = threadIdx.x & 31;
    const int row  = blockIdx.x * 8 + warp;          // 0..65535

    const float4* p = (const float4*)(L + (size_t)row * DD);
    float4 v[8];
    float m = -3.4e38f;
    #pragma unroll
    for (int j = 0; j < 8; ++j) {
        v[j] = p[j * 32 + lane];
        m = fmaxf(m, fmaxf(fmaxf(v[j].x, v[j].y), fmaxf(v[j].z, v[j].w)));
    }
    #pragma unroll
    for (int o = 16; o; o >>= 1)
        m = fmaxf(m, __shfl_xor_sync(0xffffffffu, m, o));

    float s = 0.f;
    #pragma unroll
    for (int j = 0; j < 8; ++j) {
        s += __expf(v[j].x - m) + __expf(v[j].y - m) +
             __expf(v[j].z - m) + __expf(v[j].w - m);
    }
    #pragma unroll
    for (int o = 16; o; o >>= 1)
        s += __shfl_xor_sync(0xffffffffu, s, o);

    if (lane == 0) {
        g_rowmax[row] = m;
        g_rowinv[row] = 1.f / s;
    }
}

// ============================================================================
// P4: finalize. W[i,b,d] = exp(L - max)*inv (in place), and
// ctx[i,d] = sum_b W[i,b,d] * FV[i,b,d].
// One block per i; thread t owns d = t*4..t*4+3 (full D=1024 via float4).
// ============================================================================
__global__ __launch_bounds__(256) void finalize_kernel(
    float* __restrict__ W, const float* __restrict__ FV, float* __restrict__ ctx)
{
    const int i = blockIdx.x;
    const int t = threadIdx.x;
    __shared__ float smax[256];
    __shared__ float sinv[256];
    smax[t] = g_rowmax[i * BB + t];
    sinv[t] = g_rowinv[i * BB + t];
    __syncthreads();

    const size_t base = (size_t)i * BB * DD + (size_t)t * 4;
    float cx = 0.f, cy = 0.f, cz = 0.f, cw = 0.f;

    #pragma unroll 4
    for (int b = 0; b < BB; ++b) {
        const size_t off = base + (size_t)b * DD;
        float4 l = *(const float4*)(W + off);
        float4 f = *(const float4*)(FV + off);
        const float m = smax[b], iv = sinv[b];
        float4 w;
        w.x = __expf(l.x - m) * iv;
        w.y = __expf(l.y - m) * iv;
        w.z = __expf(l.z - m) * iv;
        w.w = __expf(l.w - m) * iv;
        *(float4*)(W + off) = w;
        cx = fmaf(w.x, f.x, cx);
        cy = fmaf(w.y, f.y, cy);
        cz = fmaf(w.z, f.z, cz);
        cw = fmaf(w.w, f.w, cw);
    }
    float4 o = {cx, cy, cz, cw};
    *(float4*)(ctx + (size_t)i * DD + (size_t)t * 4) = o;
}

// ============================================================================
// launch
// ============================================================================
extern "C" void kernel_launch(void* const* d_in, const int* in_sizes, int n_in,
                              void* d_out, int out_size)
{
    (void)in_sizes; (void)n_in; (void)out_size;
    const float* FV    = (const float*)d_in[0];  // [256,256,1024]
    const float* state = (const float*)d_in[1];  // [256,1024]
    const float* Q     = (const float*)d_in[2];  // [1024,1024]
    const float* Kmat  = (const float*)d_in[3];  // [1024,256]

    float* ctx = (float*)d_out;                          // [256,1024]
    float* W   = (float*)d_out + (size_t)BB * DD;        // [256,256,1024]

    gemm_state_qt<<<dim3(SS / 64, BB / 64), 256>>>(state, Q);
    gemm_a_k     <<<dim3(NN / 64, BB / 64), 256>>>(Kmat);
    logits_kernel<<<dim3(DD / 128, BB / 128, BB), 256>>>(FV, W);
    stats_kernel <<<(BB * BB) / 8, 256>>>(W);
    finalize_kernel<<<BB, 256>>>(W, FV, ctx);
}

// round 13
// speedup vs baseline: 1.5620x; 1.5620x over previous
#include <cuda_runtime.h>
#include <cuda_bf16.h>
#include <cstdint>
#include <math.h>

// Problem constants
#define BB 256   // batch == N
#define NN 256   // feature vectors per sample
#define DD 1024  // feature dim
#define SS 1024  // state dim

// ----- device scratch (allocation-free rule: __device__ globals) -----
__device__ __align__(16) float g_A[BB * SS];            // state @ Q^T
__device__ __align__(16) float g_M[BB * NN];            // A @ K
__device__ __align__(16) float g_rowmax[BB * BB];
__device__ __align__(16) float g_rowinv[BB * BB];
__device__ __align__(16) float g_pmax[BB * BB * 16];    // partial max per 64-col slab
__device__ __align__(16) float g_psum[BB * BB * 16];    // partial sumexp
__device__ __align__(16) __nv_bfloat16 g_Mhi[BB * NN];
__device__ __align__(16) __nv_bfloat16 g_Mlo[BB * NN];
// FV split hi/lo, SAME layout as FV: [i][n][d]
__device__ __align__(16) __nv_bfloat16 g_FVhi[(size_t)BB * NN * DD];
__device__ __align__(16) __nv_bfloat16 g_FVlo[(size_t)BB * NN * DD];

// ===========================================================================
// helpers
// ===========================================================================
static __device__ __forceinline__ uint32_t smem_u32(const void* p) {
    uint32_t a;
    asm("{ .reg .u64 t; cvta.to.shared.u64 t, %1; cvt.u32.u64 %0, t; }"
        : "=r"(a) : "l"(p));
    return a;
}
#define SWZ(x) ((x) ^ (((x) >> 3) & 0x70))

static __device__ __forceinline__ void cpasync16(uint32_t dst, const void* src) {
    asm volatile("cp.async.cg.shared.global [%0], [%1], 16;"
                 :: "r"(dst), "l"(src) : "memory");
}
static __device__ __forceinline__ void ldsm4(uint32_t* r, uint32_t a) {
    asm volatile("ldmatrix.sync.aligned.m8n8.x4.shared.b16 {%0,%1,%2,%3}, [%4];"
                 : "=r"(r[0]), "=r"(r[1]), "=r"(r[2]), "=r"(r[3]) : "r"(a));
}
static __device__ __forceinline__ void ldsm4t(uint32_t* r, uint32_t a) {
    asm volatile("ldmatrix.sync.aligned.m8n8.x4.trans.shared.b16 {%0,%1,%2,%3}, [%4];"
                 : "=r"(r[0]), "=r"(r[1]), "=r"(r[2]), "=r"(r[3]) : "r"(a));
}
static __device__ __forceinline__ void mma16816(float* c, const uint32_t* a,
                                                uint32_t b0, uint32_t b1) {
    asm volatile(
        "mma.sync.aligned.m16n8k16.row.col.f32.bf16.bf16.f32 "
        "{%0,%1,%2,%3}, {%4,%5,%6,%7}, {%8,%9}, {%0,%1,%2,%3};"
        : "+f"(c[0]), "+f"(c[1]), "+f"(c[2]), "+f"(c[3])
        : "r"(a[0]), "r"(a[1]), "r"(a[2]), "r"(a[3]), "r"(b0), "r"(b1));
}

// ===========================================================================
// P1a: A[b,s] = sum_k state[b,k] * Q[s,k]
// ===========================================================================
__global__ __launch_bounds__(256) void gemm_state_qt(
    const float* __restrict__ state, const float* __restrict__ Q)
{
    __shared__ __align__(16) float As[16][64];
    __shared__ __align__(16) float Bs[16][64];
    const int tid = threadIdx.x;
    const int sBase = blockIdx.x * 64, bBase = blockIdx.y * 64;
    const int tx = tid & 15, ty = tid >> 4;
    const int r = tid >> 2, kk4 = (tid & 3) * 4;
    float acc[4][4] = {};
    for (int k0 = 0; k0 < SS; k0 += 16) {
        float4 va = *(const float4*)&state[(size_t)(bBase + r) * SS + k0 + kk4];
        float4 vb = *(const float4*)&Q[(size_t)(sBase + r) * SS + k0 + kk4];
        __syncthreads();
        As[kk4+0][r]=va.x; As[kk4+1][r]=va.y; As[kk4+2][r]=va.z; As[kk4+3][r]=va.w;
        Bs[kk4+0][r]=vb.x; Bs[kk4+1][r]=vb.y; Bs[kk4+2][r]=vb.z; Bs[kk4+3][r]=vb.w;
        __syncthreads();
        #pragma unroll
        for (int kk = 0; kk < 16; ++kk) {
            float4 a4 = *(const float4*)&As[kk][ty*4];
            float4 b4 = *(const float4*)&Bs[kk][tx*4];
            float a[4]={a4.x,a4.y,a4.z,a4.w}, b[4]={b4.x,b4.y,b4.z,b4.w};
            #pragma unroll
            for (int x=0;x<4;++x)
                #pragma unroll
                for (int y=0;y<4;++y) acc[x][y]=fmaf(a[x],b[y],acc[x][y]);
        }
    }
    #pragma unroll
    for (int x=0;x<4;++x) {
        float4 o={acc[x][0],acc[x][1],acc[x][2],acc[x][3]};
        *(float4*)&g_A[(size_t)(bBase+ty*4+x)*SS + sBase + tx*4] = o;
    }
}

// ===========================================================================
// P1b: M[b,n] = sum_s A[b,s] * K[s,n]
// ===========================================================================
__global__ __launch_bounds__(256) void gemm_a_k(const float* __restrict__ Kmat)
{
    __shared__ __align__(16) float As[16][64];
    __shared__ __align__(16) float Bs[16][64];
    const int tid = threadIdx.x;
    const int nBase = blockIdx.x * 64, bBase = blockIdx.y * 64;
    const int tx = tid & 15, ty = tid >> 4;
    const int r = tid >> 2, kk4 = (tid & 3) * 4;
    const int kkb = tid >> 4, nn4 = (tid & 15) * 4;
    float acc[4][4] = {};
    for (int k0 = 0; k0 < SS; k0 += 16) {
        float4 va = *(const float4*)&g_A[(size_t)(bBase + r) * SS + k0 + kk4];
        float4 vb = *(const float4*)&Kmat[(size_t)(k0 + kkb) * NN + nBase + nn4];
        __syncthreads();
        As[kk4+0][r]=va.x; As[kk4+1][r]=va.y; As[kk4+2][r]=va.z; As[kk4+3][r]=va.w;
        *(float4*)&Bs[kkb][nn4] = vb;
        __syncthreads();
        #pragma unroll
        for (int kk = 0; kk < 16; ++kk) {
            float4 a4 = *(const float4*)&As[kk][ty*4];
            float4 b4 = *(const float4*)&Bs[kk][tx*4];
            float a[4]={a4.x,a4.y,a4.z,a4.w}, b[4]={b4.x,b4.y,b4.z,b4.w};
            #pragma unroll
            for (int x=0;x<4;++x)
                #pragma unroll
                for (int y=0;y<4;++y) acc[x][y]=fmaf(a[x],b[y],acc[x][y]);
        }
    }
    #pragma unroll
    for (int x=0;x<4;++x) {
        float4 o={acc[x][0],acc[x][1],acc[x][2],acc[x][3]};
        *(float4*)&g_M[(size_t)(bBase+ty*4+x)*NN + nBase + tx*4] = o;
    }
}

// ===========================================================================
// Split M into bf16 hi/lo
// ===========================================================================
__global__ __launch_bounds__(256) void convert_m()
{
    int idx = blockIdx.x * 256 + threadIdx.x;
    float v = g_M[idx];
    __nv_bfloat16 hi = __float2bfloat16(v);
    g_Mhi[idx] = hi;
    g_Mlo[idx] = __float2bfloat16(v - __bfloat162float(hi));
}

// ===========================================================================
// Split FV into bf16 hi/lo (same [i][n][d] layout; no transpose needed —
// ldmatrix.trans supplies the col-major B fragments).
// ===========================================================================
struct __align__(8) bf16x4 { __nv_bfloat162 a, b; };

__global__ __launch_bounds__(256) void convert_fv(const float* __restrict__ FV)
{
    size_t idx = ((size_t)blockIdx.x * 256 + threadIdx.x) * 4;
    float4 v = *(const float4*)(FV + idx);
    __nv_bfloat16 h0 = __float2bfloat16(v.x);
    __nv_bfloat16 h1 = __float2bfloat16(v.y);
    __nv_bfloat16 h2 = __float2bfloat16(v.z);
    __nv_bfloat16 h3 = __float2bfloat16(v.w);
    __nv_bfloat16 l0 = __float2bfloat16(v.x - __bfloat162float(h0));
    __nv_bfloat16 l1 = __float2bfloat16(v.y - __bfloat162float(h1));
    __nv_bfloat16 l2 = __float2bfloat16(v.z - __bfloat162float(h2));
    __nv_bfloat16 l3 = __float2bfloat16(v.w - __bfloat162float(h3));
    bf16x4 hv; hv.a = __nv_bfloat162(h0, h1); hv.b = __nv_bfloat162(h2, h3);
    bf16x4 lv; lv.a = __nv_bfloat162(l0, l1); lv.b = __nv_bfloat162(l2, l3);
    *(bf16x4*)(g_FVhi + idx) = hv;
    *(bf16x4*)(g_FVlo + idx) = lv;
}

// ===========================================================================
// P2: logits via warp-level bf16 mma.sync, 3-term split, fp32 register accum.
// CTA: 256 thr (8 warps as 4b x 2d), tile 128(b) x 128(d), K=256 in 4 chunks
// of 64, cp.async double-buffered. Epilogue stores L (32B-sector coalesced)
// and fuses per-64-d-slab softmax partial stats.
// SMEM per buf: Ahi 16K | Alo 16K | Bhi 16K | Blo 16K ; x2 bufs = 128KB.
// ===========================================================================
#define LOGITS_SMEM (8 * 16384)

__global__ __launch_bounds__(256, 1) void logits_mma(float* __restrict__ L)
{
    extern __shared__ char dsm[];
    const uint32_t sb = smem_u32(dsm);
    const int tid = threadIdx.x, lane = tid & 31, wid = tid >> 5;
    const int bwarp = wid >> 1, dwarp = wid & 1;
    const int dBase = blockIdx.x * 128, bBase = blockIdx.y * 128;
    const int i = blockIdx.z;

    float acc[2][8][4] = {};

    auto load_chunk = [&](int s, int buf) {
        const int k0 = s * 64;
        const uint32_t Ah = sb + buf * 65536;
        const uint32_t Al = Ah + 16384, Bh = Al + 16384, Bl = Bh + 16384;
        // A tile: 128 b-rows x 64 n (128B rows, SW128)
        #pragma unroll
        for (int j = 0; j < 4; ++j) {
            int v = tid + j * 256, row = v >> 3, c = v & 7;
            uint32_t off = SWZ((uint32_t)(row * 128 + c * 16));
            size_t gi = (size_t)(bBase + row) * NN + k0 + c * 8;
            cpasync16(Ah + off, g_Mhi + gi);
            cpasync16(Al + off, g_Mlo + gi);
        }
        // B tile: 64 n-rows x 128 d (256B rows, chunk ^= row&7 swizzle)
        #pragma unroll
        for (int j = 0; j < 4; ++j) {
            int v = tid + j * 256, row = v >> 4, c = v & 15;
            uint32_t off = (uint32_t)(row * 256 + (c ^ (row & 7)) * 16);
            size_t gi = ((size_t)i * NN + k0 + row) * DD + dBase + c * 8;
            cpasync16(Bh + off, g_FVhi + gi);
            cpasync16(Bl + off, g_FVlo + gi);
        }
        asm volatile("cp.async.commit_group;" ::: "memory");
    };

    auto compute_chunk = [&](int buf) {
        const uint32_t Ah = sb + buf * 65536;
        const uint32_t Al = Ah + 16384, Bh = Al + 16384, Bl = Bh + 16384;
        #pragma unroll
        for (int kk = 0; kk < 4; ++kk) {
            uint32_t ah[2][4], al[2][4];
            #pragma unroll
            for (int m = 0; m < 2; ++m) {
                int r = bwarp * 32 + m * 16 + (lane & 15);
                uint32_t off = SWZ((uint32_t)(r * 128 + kk * 32 + (lane >> 4) * 16));
                ldsm4(ah[m], Ah + off);
                ldsm4(al[m], Al + off);
            }
            #pragma unroll
            for (int g = 0; g < 4; ++g) {
                int r = kk * 16 + (lane & 15);
                int d = dwarp * 64 + g * 16 + (lane >> 4) * 8;
                uint32_t off = (uint32_t)(r * 256 + (((d >> 3) ^ (r & 7)) * 16));
                uint32_t bh[4], bl[4];
                ldsm4t(bh, Bh + off);
                ldsm4t(bl, Bl + off);
                #pragma unroll
                for (int m = 0; m < 2; ++m) {
                    mma16816(acc[m][2*g],   ah[m], bh[0], bh[1]);
                    mma16816(acc[m][2*g+1], ah[m], bh[2], bh[3]);
                    mma16816(acc[m][2*g],   ah[m], bl[0], bl[1]);
                    mma16816(acc[m][2*g+1], ah[m], bl[2], bl[3]);
                    mma16816(acc[m][2*g],   al[m], bh[0], bh[1]);
                    mma16816(acc[m][2*g+1], al[m], bh[2], bh[3]);
                }
            }
        }
    };

    load_chunk(0, 0);
    #pragma unroll
    for (int s = 0; s < 4; ++s) {
        if (s < 3) {
            load_chunk(s + 1, (s + 1) & 1);
            asm volatile("cp.async.wait_group 1;" ::: "memory");
        } else {
            asm volatile("cp.async.wait_group 0;" ::: "memory");
        }
        __syncthreads();
        compute_chunk(s & 1);
        __syncthreads();
    }

    // -------- epilogue: fused partial softmax stats + coalesced L stores ----
    const int r4 = lane >> 2, c2 = (lane & 3) * 2;
    const int slab = blockIdx.x * 2 + dwarp;  // 16 slabs of 64 d-cols

    #pragma unroll
    for (int m = 0; m < 2; ++m) {
        #pragma unroll
        for (int h = 0; h < 2; ++h) {
            const int row = bBase + bwarp * 32 + m * 16 + h * 8 + r4;
            // per-thread stats over this row's 16 values (8 n-tiles x 2 cols)
            float mx = -3.4e38f;
            #pragma unroll
            for (int nt = 0; nt < 8; ++nt)
                mx = fmaxf(mx, fmaxf(acc[m][nt][2*h], acc[m][nt][2*h+1]));
            float sum = 0.f;
            #pragma unroll
            for (int nt = 0; nt < 8; ++nt)
                sum += __expf(acc[m][nt][2*h] - mx) + __expf(acc[m][nt][2*h+1] - mx);
            // reduce across the 4 lanes sharing this row (xor 1, 2)
            #pragma unroll
            for (int o = 1; o < 4; o <<= 1) {
                float m2 = __shfl_xor_sync(0xffffffffu, mx, o);
                float s2 = __shfl_xor_sync(0xffffffffu, sum, o);
                float Mx = fmaxf(mx, m2);
                sum = sum * __expf(mx - Mx) + s2 * __expf(m2 - Mx);
                mx = Mx;
            }
            if ((lane & 3) == 0) {
                int prow = i * BB + row;
                g_pmax[prow * 16 + slab] = mx;
                g_psum[prow * 16 + slab] = sum;
            }
            // stores: float2 per n-tile, 32B sector-coalesced
            const size_t ob = ((size_t)i * BB + row) * DD + dBase + dwarp * 64 + c2;
            #pragma unroll
            for (int nt = 0; nt < 8; ++nt) {
                float2 v = {acc[m][nt][2*h], acc[m][nt][2*h+1]};
                *(float2*)(L + ob + nt * 8) = v;
            }
        }
    }
}

// ===========================================================================
// P3: merge 16 partial (max, sumexp) slabs per (i,b) row.
// ===========================================================================
__global__ __launch_bounds__(256) void merge_stats()
{
    int r = blockIdx.x * 256 + threadIdx.x;  // 0..65535
    float pm[16], ps[16];
    #pragma unroll
    for (int j = 0; j < 16; ++j) { pm[j] = g_pmax[r*16+j]; ps[j] = g_psum[r*16+j]; }
    float M = pm[0];
    #pragma unroll
    for (int j = 1; j < 16; ++j) M = fmaxf(M, pm[j]);
    float S = 0.f;
    #pragma unroll
    for (int j = 0; j < 16; ++j) S += ps[j] * __expf(pm[j] - M);
    g_rowmax[r] = M;
    g_rowinv[r] = 1.f / S;
}

// ===========================================================================
// P4: finalize. W = exp(L - max)*inv (in place), ctx = sum_b W * FV.
// ===========================================================================
__global__ __launch_bounds__(256) void finalize_kernel(
    float* __restrict__ W, const float* __restrict__ FV, float* __restrict__ ctx)
{
    const int i = blockIdx.x;
    const int t = threadIdx.x;
    __shared__ float smax[256];
    __shared__ float sinv[256];
    smax[t] = g_rowmax[i * BB + t];
    sinv[t] = g_rowinv[i * BB + t];
    __syncthreads();

    const size_t base = (size_t)i * BB * DD + (size_t)t * 4;
    float cx = 0.f, cy = 0.f, cz = 0.f, cw = 0.f;

    #pragma unroll 4
    for (int b = 0; b < BB; ++b) {
        const size_t off = base + (size_t)b * DD;
        float4 l = *(const float4*)(W + off);
        float4 f = *(const float4*)(FV + off);
        const float m = smax[b], iv = sinv[b];
        float4 w;
        w.x = __expf(l.x - m) * iv;
        w.y = __expf(l.y - m) * iv;
        w.z = __expf(l.z - m) * iv;
        w.w = __expf(l.w - m) * iv;
        *(float4*)(W + off) = w;
        cx = fmaf(w.x, f.x, cx);
        cy = fmaf(w.y, f.y, cy);
        cz = fmaf(w.z, f.z, cz);
        cw = fmaf(w.w, f.w, cw);
    }
    float4 o = {cx, cy, cz, cw};
    *(float4*)(ctx + (size_t)i * DD + (size_t)t * 4) = o;
}

// ===========================================================================
// launch
// ===========================================================================
extern "C" void kernel_launch(void* const* d_in, const int* in_sizes, int n_in,
                              void* d_out, int out_size)
{
    (void)in_sizes; (void)n_in; (void)out_size;
    const float* FV    = (const float*)d_in[0];  // [256,256,1024]
    const float* state = (const float*)d_in[1];  // [256,1024]
    const float* Q     = (const float*)d_in[2];  // [1024,1024]
    const float* Kmat  = (const float*)d_in[3];  // [1024,256]

    float* ctx = (float*)d_out;                      // [256,1024]
    float* W   = (float*)d_out + (size_t)BB * DD;    // [256,256,1024]

    cudaFuncSetAttribute(logits_mma, cudaFuncAttributeMaxDynamicSharedMemorySize,
                         LOGITS_SMEM);

    gemm_state_qt<<<dim3(SS / 64, BB / 64), 256>>>(state, Q);
    gemm_a_k     <<<dim3(NN / 64, BB / 64), 256>>>(Kmat);
    convert_m    <<<BB * NN / 256, 256>>>();
    convert_fv   <<<(int)(((size_t)BB * NN * DD) / 4 / 256), 256>>>(FV);
    logits_mma   <<<dim3(DD / 128, BB / 128, BB), 256, LOGITS_SMEM>>>(W);
    merge_stats  <<<(BB * BB) / 256, 256>>>();
    finalize_kernel<<<BB, 256>>>(W, FV, ctx);
}

// round 14
// speedup vs baseline: 1.5624x; 1.0003x over previous
#include <cuda_runtime.h>
#include <cuda_bf16.h>
#include <cstdint>
#include <math.h>

// Problem constants
#define BB 256   // batch == N
#define NN 256   // feature vectors per sample
#define DD 1024  // feature dim
#define SS 1024  // state dim

// ----- device scratch (allocation-free rule: __device__ globals) -----
__device__ __align__(16) float g_A[BB * SS];            // state @ Q^T
__device__ __align__(16) float g_M[BB * NN];            // A @ K
__device__ __align__(16) float g_rowmax[BB * BB];
__device__ __align__(16) float g_rowinv[BB * BB];
__device__ __align__(16) float g_pmax[BB * BB * 16];    // partial max per 64-col slab
__device__ __align__(16) float g_psum[BB * BB * 16];    // partial sumexp
__device__ __align__(16) __nv_bfloat16 g_Mhi[BB * NN];
__device__ __align__(16) __nv_bfloat16 g_Mlo[BB * NN];
// FV split hi/lo, SAME layout as FV: [i][n][d]
__device__ __align__(16) __nv_bfloat16 g_FVhi[(size_t)BB * NN * DD];
__device__ __align__(16) __nv_bfloat16 g_FVlo[(size_t)BB * NN * DD];

// ===========================================================================
// helpers
// ===========================================================================
static __device__ __forceinline__ uint32_t smem_u32(const void* p) {
    uint32_t a;
    asm("{ .reg .u64 t; cvta.to.shared.u64 t, %1; cvt.u32.u64 %0, t; }"
        : "=r"(a) : "l"(p));
    return a;
}
#define SWZ(x) ((x) ^ (((x) >> 3) & 0x70))

static __device__ __forceinline__ void cpasync16(uint32_t dst, const void* src) {
    asm volatile("cp.async.cg.shared.global [%0], [%1], 16;"
                 :: "r"(dst), "l"(src) : "memory");
}
static __device__ __forceinline__ void ldsm4(uint32_t* r, uint32_t a) {
    asm volatile("ldmatrix.sync.aligned.m8n8.x4.shared.b16 {%0,%1,%2,%3}, [%4];"
                 : "=r"(r[0]), "=r"(r[1]), "=r"(r[2]), "=r"(r[3]) : "r"(a));
}
static __device__ __forceinline__ void ldsm4t(uint32_t* r, uint32_t a) {
    asm volatile("ldmatrix.sync.aligned.m8n8.x4.trans.shared.b16 {%0,%1,%2,%3}, [%4];"
                 : "=r"(r[0]), "=r"(r[1]), "=r"(r[2]), "=r"(r[3]) : "r"(a));
}
static __device__ __forceinline__ void mma16816(float* c, const uint32_t* a,
                                                uint32_t b0, uint32_t b1) {
    asm volatile(
        "mma.sync.aligned.m16n8k16.row.col.f32.bf16.bf16.f32 "
        "{%0,%1,%2,%3}, {%4,%5,%6,%7}, {%8,%9}, {%0,%1,%2,%3};"
        : "+f"(c[0]), "+f"(c[1]), "+f"(c[2]), "+f"(c[3])
        : "r"(a[0]), "r"(a[1]), "r"(a[2]), "r"(a[3]), "r"(b0), "r"(b1));
}

// ===========================================================================
// P1a: A[b,s] = sum_k state[b,k] * Q[s,k]
// ===========================================================================
__global__ __launch_bounds__(256) void gemm_state_qt(
    const float* __restrict__ state, const float* __restrict__ Q)
{
    __shared__ __align__(16) float As[16][64];
    __shared__ __align__(16) float Bs[16][64];
    const int tid = threadIdx.x;
    const int sBase = blockIdx.x * 64, bBase = blockIdx.y * 64;
    const int tx = tid & 15, ty = tid >> 4;
    const int r = tid >> 2, kk4 = (tid & 3) * 4;
    float acc[4][4] = {};
    for (int k0 = 0; k0 < SS; k0 += 16) {
        float4 va = *(const float4*)&state[(size_t)(bBase + r) * SS + k0 + kk4];
        float4 vb = *(const float4*)&Q[(size_t)(sBase + r) * SS + k0 + kk4];
        __syncthreads();
        As[kk4+0][r]=va.x; As[kk4+1][r]=va.y; As[kk4+2][r]=va.z; As[kk4+3][r]=va.w;
        Bs[kk4+0][r]=vb.x; Bs[kk4+1][r]=vb.y; Bs[kk4+2][r]=vb.z; Bs[kk4+3][r]=vb.w;
        __syncthreads();
        #pragma unroll
        for (int kk = 0; kk < 16; ++kk) {
            float4 a4 = *(const float4*)&As[kk][ty*4];
            float4 b4 = *(const float4*)&Bs[kk][tx*4];
            float a[4]={a4.x,a4.y,a4.z,a4.w}, b[4]={b4.x,b4.y,b4.z,b4.w};
            #pragma unroll
            for (int x=0;x<4;++x)
                #pragma unroll
                for (int y=0;y<4;++y) acc[x][y]=fmaf(a[x],b[y],acc[x][y]);
        }
    }
    #pragma unroll
    for (int x=0;x<4;++x) {
        float4 o={acc[x][0],acc[x][1],acc[x][2],acc[x][3]};
        *(float4*)&g_A[(size_t)(bBase+ty*4+x)*SS + sBase + tx*4] = o;
    }
}

// ===========================================================================
// P1b: M[b,n] = sum_s A[b,s] * K[s,n]
// ===========================================================================
__global__ __launch_bounds__(256) void gemm_a_k(const float* __restrict__ Kmat)
{
    __shared__ __align__(16) float As[16][64];
    __shared__ __align__(16) float Bs[16][64];
    const int tid = threadIdx.x;
    const int nBase = blockIdx.x * 64, bBase = blockIdx.y * 64;
    const int tx = tid & 15, ty = tid >> 4;
    const int r = tid >> 2, kk4 = (tid & 3) * 4;
    const int kkb = tid >> 4, nn4 = (tid & 15) * 4;
    float acc[4][4] = {};
    for (int k0 = 0; k0 < SS; k0 += 16) {
        float4 va = *(const float4*)&g_A[(size_t)(bBase + r) * SS + k0 + kk4];
        float4 vb = *(const float4*)&Kmat[(size_t)(k0 + kkb) * NN + nBase + nn4];
        __syncthreads();
        As[kk4+0][r]=va.x; As[kk4+1][r]=va.y; As[kk4+2][r]=va.z; As[kk4+3][r]=va.w;
        *(float4*)&Bs[kkb][nn4] = vb;
        __syncthreads();
        #pragma unroll
        for (int kk = 0; kk < 16; ++kk) {
            float4 a4 = *(const float4*)&As[kk][ty*4];
            float4 b4 = *(const float4*)&Bs[kk][tx*4];
            float a[4]={a4.x,a4.y,a4.z,a4.w}, b[4]={b4.x,b4.y,b4.z,b4.w};
            #pragma unroll
            for (int x=0;x<4;++x)
                #pragma unroll
                for (int y=0;y<4;++y) acc[x][y]=fmaf(a[x],b[y],acc[x][y]);
        }
    }
    #pragma unroll
    for (int x=0;x<4;++x) {
        float4 o={acc[x][0],acc[x][1],acc[x][2],acc[x][3]};
        *(float4*)&g_M[(size_t)(bBase+ty*4+x)*NN + nBase + tx*4] = o;
    }
}

// ===========================================================================
// Split M into bf16 hi/lo
// ===========================================================================
__global__ __launch_bounds__(256) void convert_m()
{
    int idx = blockIdx.x * 256 + threadIdx.x;
    float v = g_M[idx];
    __nv_bfloat16 hi = __float2bfloat16(v);
    g_Mhi[idx] = hi;
    g_Mlo[idx] = __float2bfloat16(v - __bfloat162float(hi));
}

// ===========================================================================
// Split FV into bf16 hi/lo (same [i][n][d] layout; no transpose needed —
// ldmatrix.trans supplies the col-major B fragments).
// ===========================================================================
struct __align__(8) bf16x4 { __nv_bfloat162 a, b; };

__global__ __launch_bounds__(256) void convert_fv(const float* __restrict__ FV)
{
    size_t idx = ((size_t)blockIdx.x * 256 + threadIdx.x) * 4;
    float4 v = *(const float4*)(FV + idx);
    __nv_bfloat16 h0 = __float2bfloat16(v.x);
    __nv_bfloat16 h1 = __float2bfloat16(v.y);
    __nv_bfloat16 h2 = __float2bfloat16(v.z);
    __nv_bfloat16 h3 = __float2bfloat16(v.w);
    __nv_bfloat16 l0 = __float2bfloat16(v.x - __bfloat162float(h0));
    __nv_bfloat16 l1 = __float2bfloat16(v.y - __bfloat162float(h1));
    __nv_bfloat16 l2 = __float2bfloat16(v.z - __bfloat162float(h2));
    __nv_bfloat16 l3 = __float2bfloat16(v.w - __bfloat162float(h3));
    bf16x4 hv; hv.a = __nv_bfloat162(h0, h1); hv.b = __nv_bfloat162(h2, h3);
    bf16x4 lv; lv.a = __nv_bfloat162(l0, l1); lv.b = __nv_bfloat162(l2, l3);
    *(bf16x4*)(g_FVhi + idx) = hv;
    *(bf16x4*)(g_FVlo + idx) = lv;
}

// ===========================================================================
// P2: logits via warp-level bf16 mma.sync, 3-term split, fp32 register accum.
// CTA: 256 thr (8 warps as 4b x 2d), tile 128(b) x 128(d), K=256 in 4 chunks
// of 64, cp.async double-buffered. Epilogue stores L (32B-sector coalesced)
// and fuses per-64-d-slab softmax partial stats.
// SMEM per buf: Ahi 16K | Alo 16K | Bhi 16K | Blo 16K ; x2 bufs = 128KB.
// ===========================================================================
#define LOGITS_SMEM (8 * 16384)

__global__ __launch_bounds__(256, 1) void logits_mma(float* __restrict__ L)
{
    extern __shared__ char dsm[];
    const uint32_t sb = smem_u32(dsm);
    const int tid = threadIdx.x, lane = tid & 31, wid = tid >> 5;
    const int bwarp = wid >> 1, dwarp = wid & 1;
    const int dBase = blockIdx.x * 128, bBase = blockIdx.y * 128;
    const int i = blockIdx.z;

    float acc[2][8][4] = {};

    auto load_chunk = [&](int s, int buf) {
        const int k0 = s * 64;
        const uint32_t Ah = sb + buf * 65536;
        const uint32_t Al = Ah + 16384, Bh = Al + 16384, Bl = Bh + 16384;
        // A tile: 128 b-rows x 64 n (128B rows, SW128)
        #pragma unroll
        for (int j = 0; j < 4; ++j) {
            int v = tid + j * 256, row = v >> 3, c = v & 7;
            uint32_t off = SWZ((uint32_t)(row * 128 + c * 16));
            size_t gi = (size_t)(bBase + row) * NN + k0 + c * 8;
            cpasync16(Ah + off, g_Mhi + gi);
            cpasync16(Al + off, g_Mlo + gi);
        }
        // B tile: 64 n-rows x 128 d (256B rows, chunk ^= row&7 swizzle)
        #pragma unroll
        for (int j = 0; j < 4; ++j) {
            int v = tid + j * 256, row = v >> 4, c = v & 15;
            uint32_t off = (uint32_t)(row * 256 + (c ^ (row & 7)) * 16);
            size_t gi = ((size_t)i * NN + k0 + row) * DD + dBase + c * 8;
            cpasync16(Bh + off, g_FVhi + gi);
            cpasync16(Bl + off, g_FVlo + gi);
        }
        asm volatile("cp.async.commit_group;" ::: "memory");
    };

    auto compute_chunk = [&](int buf) {
        const uint32_t Ah = sb + buf * 65536;
        const uint32_t Al = Ah + 16384, Bh = Al + 16384, Bl = Bh + 16384;
        #pragma unroll
        for (int kk = 0; kk < 4; ++kk) {
            uint32_t ah[2][4], al[2][4];
            #pragma unroll
            for (int m = 0; m < 2; ++m) {
                int r = bwarp * 32 + m * 16 + (lane & 15);
                uint32_t off = SWZ((uint32_t)(r * 128 + kk * 32 + (lane >> 4) * 16));
                ldsm4(ah[m], Ah + off);
                ldsm4(al[m], Al + off);
            }
            #pragma unroll
            for (int g = 0; g < 4; ++g) {
                int r = kk * 16 + (lane & 15);
                int d = dwarp * 64 + g * 16 + (lane >> 4) * 8;
                uint32_t off = (uint32_t)(r * 256 + (((d >> 3) ^ (r & 7)) * 16));
                uint32_t bh[4], bl[4];
                ldsm4t(bh, Bh + off);
                ldsm4t(bl, Bl + off);
                #pragma unroll
                for (int m = 0; m < 2; ++m) {
                    mma16816(acc[m][2*g],   ah[m], bh[0], bh[1]);
                    mma16816(acc[m][2*g+1], ah[m], bh[2], bh[3]);
                    mma16816(acc[m][2*g],   ah[m], bl[0], bl[1]);
                    mma16816(acc[m][2*g+1], ah[m], bl[2], bl[3]);
                    mma16816(acc[m][2*g],   al[m], bh[0], bh[1]);
                    mma16816(acc[m][2*g+1], al[m], bh[2], bh[3]);
                }
            }
        }
    };

    load_chunk(0, 0);
    #pragma unroll
    for (int s = 0; s < 4; ++s) {
        if (s < 3) {
            load_chunk(s + 1, (s + 1) & 1);
            asm volatile("cp.async.wait_group 1;" ::: "memory");
        } else {
            asm volatile("cp.async.wait_group 0;" ::: "memory");
        }
        __syncthreads();
        compute_chunk(s & 1);
        __syncthreads();
    }

    // -------- epilogue: fused partial softmax stats + coalesced L stores ----
    const int r4 = lane >> 2, c2 = (lane & 3) * 2;
    const int slab = blockIdx.x * 2 + dwarp;  // 16 slabs of 64 d-cols

    #pragma unroll
    for (int m = 0; m < 2; ++m) {
        #pragma unroll
        for (int h = 0; h < 2; ++h) {
            const int row = bBase + bwarp * 32 + m * 16 + h * 8 + r4;
            // per-thread stats over this row's 16 values (8 n-tiles x 2 cols)
            float mx = -3.4e38f;
            #pragma unroll
            for (int nt = 0; nt < 8; ++nt)
                mx = fmaxf(mx, fmaxf(acc[m][nt][2*h], acc[m][nt][2*h+1]));
            float sum = 0.f;
            #pragma unroll
            for (int nt = 0; nt < 8; ++nt)
                sum += __expf(acc[m][nt][2*h] - mx) + __expf(acc[m][nt][2*h+1] - mx);
            // reduce across the 4 lanes sharing this row (xor 1, 2)
            #pragma unroll
            for (int o = 1; o < 4; o <<= 1) {
                float m2 = __shfl_xor_sync(0xffffffffu, mx, o);
                float s2 = __shfl_xor_sync(0xffffffffu, sum, o);
                float Mx = fmaxf(mx, m2);
                sum = sum * __expf(mx - Mx) + s2 * __expf(m2 - Mx);
                mx = Mx;
            }
            if ((lane & 3) == 0) {
                int prow = i * BB + row;
                g_pmax[prow * 16 + slab] = mx;
                g_psum[prow * 16 + slab] = sum;
            }
            // stores: float2 per n-tile, 32B sector-coalesced
            const size_t ob = ((size_t)i * BB + row) * DD + dBase + dwarp * 64 + c2;
            #pragma unroll
            for (int nt = 0; nt < 8; ++nt) {
                float2 v = {acc[m][nt][2*h], acc[m][nt][2*h+1]};
                *(float2*)(L + ob + nt * 8) = v;
            }
        }
    }
}

// ===========================================================================
// P3: merge 16 partial (max, sumexp) slabs per (i,b) row.
// ===========================================================================
__global__ __launch_bounds__(256) void merge_stats()
{
    int r = blockIdx.x * 256 + threadIdx.x;  // 0..65535
    float pm[16], ps[16];
    #pragma unroll
    for (int j = 0; j < 16; ++j) { pm[j] = g_pmax[r*16+j]; ps[j] = g_psum[r*16+j]; }
    float M = pm[0];
    #pragma unroll
    for (int j = 1; j < 16; ++j) M = fmaxf(M, pm[j]);
    float S = 0.f;
    #pragma unroll
    for (int j = 0; j < 16; ++j) S += ps[j] * __expf(pm[j] - M);
    g_rowmax[r] = M;
    g_rowinv[r] = 1.f / S;
}

// ===========================================================================
// P4: finalize. W = exp(L - max)*inv (in place), ctx = sum_b W * FV.
// ===========================================================================
__global__ __launch_bounds__(256) void finalize_kernel(
    float* __restrict__ W, const float* __restrict__ FV, float* __restrict__ ctx)
{
    const int i = blockIdx.x;
    const int t = threadIdx.x;
    __shared__ float smax[256];
    __shared__ float sinv[256];
    smax[t] = g_rowmax[i * BB + t];
    sinv[t] = g_rowinv[i * BB + t];
    __syncthreads();

    const size_t base = (size_t)i * BB * DD + (size_t)t * 4;
    float cx = 0.f, cy = 0.f, cz = 0.f, cw = 0.f;

    #pragma unroll 4
    for (int b = 0; b < BB; ++b) {
        const size_t off = base + (size_t)b * DD;
        float4 l = *(const float4*)(W + off);
        float4 f = *(const float4*)(FV + off);
        const float m = smax[b], iv = sinv[b];
        float4 w;
        w.x = __expf(l.x - m) * iv;
        w.y = __expf(l.y - m) * iv;
        w.z = __expf(l.z - m) * iv;
        w.w = __expf(l.w - m) * iv;
        *(float4*)(W + off) = w;
        cx = fmaf(w.x, f.x, cx);
        cy = fmaf(w.y, f.y, cy);
        cz = fmaf(w.z, f.z, cz);
        cw = fmaf(w.w, f.w, cw);
    }
    float4 o = {cx, cy, cz, cw};
    *(float4*)(ctx + (size_t)i * DD + (size_t)t * 4) = o;
}

// ===========================================================================
// launch
// ===========================================================================
extern "C" void kernel_launch(void* const* d_in, const int* in_sizes, int n_in,
                              void* d_out, int out_size)
{
    (void)in_sizes; (void)n_in; (void)out_size;
    const float* FV    = (const float*)d_in[0];  // [256,256,1024]
    const float* state = (const float*)d_in[1];  // [256,1024]
    const float* Q     = (const float*)d_in[2];  // [1024,1024]
    const float* Kmat  = (const float*)d_in[3];  // [1024,256]

    float* ctx = (float*)d_out;                      // [256,1024]
    float* W   = (float*)d_out + (size_t)BB * DD;    // [256,256,1024]

    cudaFuncSetAttribute(logits_mma, cudaFuncAttributeMaxDynamicSharedMemorySize,
                         LOGITS_SMEM);

    gemm_state_qt<<<dim3(SS / 64, BB / 64), 256>>>(state, Q);
    gemm_a_k     <<<dim3(NN / 64, BB / 64), 256>>>(Kmat);
    convert_m    <<<BB * NN / 256, 256>>>();
    convert_fv   <<<(int)(((size_t)BB * NN * DD) / 4 / 256), 256>>>(FV);
    logits_mma   <<<dim3(DD / 128, BB / 128, BB), 256, LOGITS_SMEM>>>(W);
    merge_stats  <<<(BB * BB) / 256, 256>>>();
    finalize_kernel<<<BB, 256>>>(W, FV, ctx);
}

// round 15
// speedup vs baseline: 1.6586x; 1.0616x over previous
#include <cuda_runtime.h>
#include <cuda_bf16.h>
#include <cstdint>
#include <math.h>

// Problem constants
#define BB 256   // batch == N
#define NN 256   // feature vectors per sample
#define DD 1024  // feature dim
#define SS 1024  // state dim

// ----- device scratch (allocation-free rule: __device__ globals) -----
__device__ __align__(16) float g_A[BB * SS];            // state @ Q^T
__device__ __align__(16) float g_M[BB * NN];            // A @ K
__device__ __align__(16) float g_rowmax[BB * BB];
__device__ __align__(16) float g_rowinv[BB * BB];
__device__ __align__(16) float g_pmax[BB * BB * 16];    // partial max per 64-col slab
__device__ __align__(16) float g_psum[BB * BB * 16];    // partial sumexp
__device__ __align__(16) __nv_bfloat16 g_Mhi[BB * NN];
__device__ __align__(16) __nv_bfloat16 g_Mlo[BB * NN];
// FV split hi/lo, SAME layout as FV: [i][n][d]
__device__ __align__(16) __nv_bfloat16 g_FVhi[(size_t)BB * NN * DD];
__device__ __align__(16) __nv_bfloat16 g_FVlo[(size_t)BB * NN * DD];

// ===========================================================================
// helpers
// ===========================================================================
static __device__ __forceinline__ uint32_t smem_u32(const void* p) {
    uint32_t a;
    asm("{ .reg .u64 t; cvta.to.shared.u64 t, %1; cvt.u32.u64 %0, t; }"
        : "=r"(a) : "l"(p));
    return a;
}
#define SWZ(x) ((x) ^ (((x) >> 3) & 0x70))

static __device__ __forceinline__ void cpasync16(uint32_t dst, const void* src) {
    asm volatile("cp.async.cg.shared.global [%0], [%1], 16;"
                 :: "r"(dst), "l"(src) : "memory");
}
static __device__ __forceinline__ void ldsm4(uint32_t* r, uint32_t a) {
    asm volatile("ldmatrix.sync.aligned.m8n8.x4.shared.b16 {%0,%1,%2,%3}, [%4];"
                 : "=r"(r[0]), "=r"(r[1]), "=r"(r[2]), "=r"(r[3]) : "r"(a));
}
static __device__ __forceinline__ void ldsm4t(uint32_t* r, uint32_t a) {
    asm volatile("ldmatrix.sync.aligned.m8n8.x4.trans.shared.b16 {%0,%1,%2,%3}, [%4];"
                 : "=r"(r[0]), "=r"(r[1]), "=r"(r[2]), "=r"(r[3]) : "r"(a));
}
static __device__ __forceinline__ void mma16816(float* c, const uint32_t* a,
                                                uint32_t b0, uint32_t b1) {
    asm volatile(
        "mma.sync.aligned.m16n8k16.row.col.f32.bf16.bf16.f32 "
        "{%0,%1,%2,%3}, {%4,%5,%6,%7}, {%8,%9}, {%0,%1,%2,%3};"
        : "+f"(c[0]), "+f"(c[1]), "+f"(c[2]), "+f"(c[3])
        : "r"(a[0]), "r"(a[1]), "r"(a[2]), "r"(a[3]), "r"(b0), "r"(b1));
}

// ===========================================================================
// P1a: A[b,s] = sum_k state[b,k] * Q[s,k]
// ===========================================================================
__global__ __launch_bounds__(256) void gemm_state_qt(
    const float* __restrict__ state, const float* __restrict__ Q)
{
    __shared__ __align__(16) float As[16][64];
    __shared__ __align__(16) float Bs[16][64];
    const int tid = threadIdx.x;
    const int sBase = blockIdx.x * 64, bBase = blockIdx.y * 64;
    const int tx = tid & 15, ty = tid >> 4;
    const int r = tid >> 2, kk4 = (tid & 3) * 4;
    float acc[4][4] = {};
    for (int k0 = 0; k0 < SS; k0 += 16) {
        float4 va = *(const float4*)&state[(size_t)(bBase + r) * SS + k0 + kk4];
        float4 vb = *(const float4*)&Q[(size_t)(sBase + r) * SS + k0 + kk4];
        __syncthreads();
        As[kk4+0][r]=va.x; As[kk4+1][r]=va.y; As[kk4+2][r]=va.z; As[kk4+3][r]=va.w;
        Bs[kk4+0][r]=vb.x; Bs[kk4+1][r]=vb.y; Bs[kk4+2][r]=vb.z; Bs[kk4+3][r]=vb.w;
        __syncthreads();
        #pragma unroll
        for (int kk = 0; kk < 16; ++kk) {
            float4 a4 = *(const float4*)&As[kk][ty*4];
            float4 b4 = *(const float4*)&Bs[kk][tx*4];
            float a[4]={a4.x,a4.y,a4.z,a4.w}, b[4]={b4.x,b4.y,b4.z,b4.w};
            #pragma unroll
            for (int x=0;x<4;++x)
                #pragma unroll
                for (int y=0;y<4;++y) acc[x][y]=fmaf(a[x],b[y],acc[x][y]);
        }
    }
    #pragma unroll
    for (int x=0;x<4;++x) {
        float4 o={acc[x][0],acc[x][1],acc[x][2],acc[x][3]};
        *(float4*)&g_A[(size_t)(bBase+ty*4+x)*SS + sBase + tx*4] = o;
    }
}

// ===========================================================================
// P1b: M[b,n] = sum_s A[b,s] * K[s,n]
// ===========================================================================
__global__ __launch_bounds__(256) void gemm_a_k(const float* __restrict__ Kmat)
{
    __shared__ __align__(16) float As[16][64];
    __shared__ __align__(16) float Bs[16][64];
    const int tid = threadIdx.x;
    const int nBase = blockIdx.x * 64, bBase = blockIdx.y * 64;
    const int tx = tid & 15, ty = tid >> 4;
    const int r = tid >> 2, kk4 = (tid & 3) * 4;
    const int kkb = tid >> 4, nn4 = (tid & 15) * 4;
    float acc[4][4] = {};
    for (int k0 = 0; k0 < SS; k0 += 16) {
        float4 va = *(const float4*)&g_A[(size_t)(bBase + r) * SS + k0 + kk4];
        float4 vb = *(const float4*)&Kmat[(size_t)(k0 + kkb) * NN + nBase + nn4];
        __syncthreads();
        As[kk4+0][r]=va.x; As[kk4+1][r]=va.y; As[kk4+2][r]=va.z; As[kk4+3][r]=va.w;
        *(float4*)&Bs[kkb][nn4] = vb;
        __syncthreads();
        #pragma unroll
        for (int kk = 0; kk < 16; ++kk) {
            float4 a4 = *(const float4*)&As[kk][ty*4];
            float4 b4 = *(const float4*)&Bs[kk][tx*4];
            float a[4]={a4.x,a4.y,a4.z,a4.w}, b[4]={b4.x,b4.y,b4.z,b4.w};
            #pragma unroll
            for (int x=0;x<4;++x)
                #pragma unroll
                for (int y=0;y<4;++y) acc[x][y]=fmaf(a[x],b[y],acc[x][y]);
        }
    }
    #pragma unroll
    for (int x=0;x<4;++x) {
        float4 o={acc[x][0],acc[x][1],acc[x][2],acc[x][3]};
        *(float4*)&g_M[(size_t)(bBase+ty*4+x)*NN + nBase + tx*4] = o;
    }
}

// ===========================================================================
// Split M into bf16 hi/lo
// ===========================================================================
__global__ __launch_bounds__(256) void convert_m()
{
    int idx = blockIdx.x * 256 + threadIdx.x;
    float v = g_M[idx];
    __nv_bfloat16 hi = __float2bfloat16(v);
    g_Mhi[idx] = hi;
    g_Mlo[idx] = __float2bfloat16(v - __bfloat162float(hi));
}

// ===========================================================================
// Split FV into bf16 hi/lo (same [i][n][d] layout)
// ===========================================================================
struct __align__(8) bf16x4 { __nv_bfloat162 a, b; };

__global__ __launch_bounds__(256) void convert_fv(const float* __restrict__ FV)
{
    size_t idx = ((size_t)blockIdx.x * 256 + threadIdx.x) * 4;
    float4 v = *(const float4*)(FV + idx);
    __nv_bfloat16 h0 = __float2bfloat16(v.x);
    __nv_bfloat16 h1 = __float2bfloat16(v.y);
    __nv_bfloat16 h2 = __float2bfloat16(v.z);
    __nv_bfloat16 h3 = __float2bfloat16(v.w);
    __nv_bfloat16 l0 = __float2bfloat16(v.x - __bfloat162float(h0));
    __nv_bfloat16 l1 = __float2bfloat16(v.y - __bfloat162float(h1));
    __nv_bfloat16 l2 = __float2bfloat16(v.z - __bfloat162float(h2));
    __nv_bfloat16 l3 = __float2bfloat16(v.w - __bfloat162float(h3));
    bf16x4 hv; hv.a = __nv_bfloat162(h0, h1); hv.b = __nv_bfloat162(h2, h3);
    bf16x4 lv; lv.a = __nv_bfloat162(l0, l1); lv.b = __nv_bfloat162(l2, l3);
    *(bf16x4*)(g_FVhi + idx) = hv;
    *(bf16x4*)(g_FVlo + idx) = lv;
}

// ===========================================================================
// P2: logits via warp-level bf16 mma.sync, 3-term split, fp32 register accum.
// CTA: 256 thr (8 warps as 4b x 2d), tile 128(b) x 128(d).
// K=256 as 8 chunks of 32, 3-stage cp.async pipeline, ONE sync per chunk.
// SMEM per stage (32KB): A rows 128B = [32n hi | 32n lo] (16KB, SW128),
//                        Bhi 32x256B (8KB), Blo (8KB).
// 3 stages = 96KB -> 2 CTAs/SM (4 warps/SMSP).
// ===========================================================================
#define LOGITS_SMEM (3 * 32768)
#define NCHUNK 8

__global__ __launch_bounds__(256, 2) void logits_mma(float* __restrict__ L)
{
    extern __shared__ char dsm[];
    const uint32_t sb = smem_u32(dsm);
    const int tid = threadIdx.x, lane = tid & 31, wid = tid >> 5;
    const int bwarp = wid >> 1, dwarp = wid & 1;
    const int dBase = blockIdx.x * 128, bBase = blockIdx.y * 128;
    const int i = blockIdx.z;

    float acc[2][8][4] = {};

    auto load_chunk = [&](int s, int stg) {
        const int k0 = s * 32;
        const uint32_t A0 = sb + stg * 32768;
        const uint32_t Bh = A0 + 16384, Bl = A0 + 24576;
        // A: 128 rows x [32n hi | 32n lo] (128B rows, SW128)
        #pragma unroll
        for (int j = 0; j < 2; ++j) {
            int v = tid + j * 256, row = v >> 2, c = v & 3;
            size_t gi = (size_t)(bBase + row) * NN + k0 + c * 8;
            cpasync16(A0 + SWZ((uint32_t)(row * 128 + c * 16)), g_Mhi + gi);
            cpasync16(A0 + SWZ((uint32_t)(row * 128 + 64 + c * 16)), g_Mlo + gi);
        }
        // B: 32 n-rows x 128 d (256B rows, c ^= row&7 swizzle)
        #pragma unroll
        for (int j = 0; j < 2; ++j) {
            int v = tid + j * 256, row = v >> 4, c = v & 15;
            uint32_t off = (uint32_t)(row * 256 + (c ^ (row & 7)) * 16);
            size_t gi = ((size_t)i * NN + k0 + row) * DD + dBase + c * 8;
            cpasync16(Bh + off, g_FVhi + gi);
            cpasync16(Bl + off, g_FVlo + gi);
        }
        asm volatile("cp.async.commit_group;" ::: "memory");
    };

    auto compute_chunk = [&](int stg) {
        const uint32_t A0 = sb + stg * 32768;
        const uint32_t Bh = A0 + 16384, Bl = A0 + 24576;
        #pragma unroll
        for (int kk = 0; kk < 2; ++kk) {
            uint32_t ah[2][4], al[2][4];
            #pragma unroll
            for (int m = 0; m < 2; ++m) {
                int r = bwarp * 32 + m * 16 + (lane & 15);
                uint32_t base = (uint32_t)(r * 128 + kk * 32 + (lane >> 4) * 16);
                ldsm4(ah[m], A0 + SWZ(base));
                ldsm4(al[m], A0 + SWZ(base + 64));
            }
            #pragma unroll
            for (int g = 0; g < 4; ++g) {
                int r = kk * 16 + (lane & 15);
                int d = dwarp * 64 + g * 16 + (lane >> 4) * 8;
                uint32_t off = (uint32_t)(r * 256 + (((d >> 3) ^ (r & 7)) * 16));
                uint32_t bh[4], bl[4];
                ldsm4t(bh, Bh + off);
                ldsm4t(bl, Bl + off);
                #pragma unroll
                for (int m = 0; m < 2; ++m) {
                    mma16816(acc[m][2*g],   ah[m], bh[0], bh[1]);
                    mma16816(acc[m][2*g+1], ah[m], bh[2], bh[3]);
                    mma16816(acc[m][2*g],   ah[m], bl[0], bl[1]);
                    mma16816(acc[m][2*g+1], ah[m], bl[2], bl[3]);
                    mma16816(acc[m][2*g],   al[m], bh[0], bh[1]);
                    mma16816(acc[m][2*g+1], al[m], bh[2], bh[3]);
                }
            }
        }
    };

    // 3-stage pipeline, one sync per chunk
    load_chunk(0, 0);
    load_chunk(1, 1);
    #pragma unroll
    for (int s = 0; s < NCHUNK; ++s) {
        if (s < NCHUNK - 1)
            asm volatile("cp.async.wait_group 1;" ::: "memory");
        else
            asm volatile("cp.async.wait_group 0;" ::: "memory");
        __syncthreads();
        compute_chunk(s % 3);
        if (s + 2 < NCHUNK) load_chunk(s + 2, (s + 2) % 3);
    }

    // -------- epilogue: fused partial softmax stats + coalesced L stores ----
    const int r4 = lane >> 2, c2 = (lane & 3) * 2;
    const int slab = blockIdx.x * 2 + dwarp;  // 16 slabs of 64 d-cols

    #pragma unroll
    for (int m = 0; m < 2; ++m) {
        #pragma unroll
        for (int h = 0; h < 2; ++h) {
            const int row = bBase + bwarp * 32 + m * 16 + h * 8 + r4;
            float mx = -3.4e38f;
            #pragma unroll
            for (int nt = 0; nt < 8; ++nt)
                mx = fmaxf(mx, fmaxf(acc[m][nt][2*h], acc[m][nt][2*h+1]));
            float sum = 0.f;
            #pragma unroll
            for (int nt = 0; nt < 8; ++nt)
                sum += __expf(acc[m][nt][2*h] - mx) + __expf(acc[m][nt][2*h+1] - mx);
            #pragma unroll
            for (int o = 1; o < 4; o <<= 1) {
                float m2 = __shfl_xor_sync(0xffffffffu, mx, o);
                float s2 = __shfl_xor_sync(0xffffffffu, sum, o);
                float Mx = fmaxf(mx, m2);
                sum = sum * __expf(mx - Mx) + s2 * __expf(m2 - Mx);
                mx = Mx;
            }
            if ((lane & 3) == 0) {
                int prow = i * BB + row;
                g_pmax[prow * 16 + slab] = mx;
                g_psum[prow * 16 + slab] = sum;
            }
            const size_t ob = ((size_t)i * BB + row) * DD + dBase + dwarp * 64 + c2;
            #pragma unroll
            for (int nt = 0; nt < 8; ++nt) {
                float2 v = {acc[m][nt][2*h], acc[m][nt][2*h+1]};
                *(float2*)(L + ob + nt * 8) = v;
            }
        }
    }
}

// ===========================================================================
// P3: merge 16 partial (max, sumexp) slabs per (i,b) row.
// ===========================================================================
__global__ __launch_bounds__(256) void merge_stats()
{
    int r = blockIdx.x * 256 + threadIdx.x;  // 0..65535
    float pm[16], ps[16];
    #pragma unroll
    for (int j = 0; j < 16; ++j) { pm[j] = g_pmax[r*16+j]; ps[j] = g_psum[r*16+j]; }
    float M = pm[0];
    #pragma unroll
    for (int j = 1; j < 16; ++j) M = fmaxf(M, pm[j]);
    float S = 0.f;
    #pragma unroll
    for (int j = 0; j < 16; ++j) S += ps[j] * __expf(pm[j] - M);
    g_rowmax[r] = M;
    g_rowinv[r] = 1.f / S;
}

// ===========================================================================
// P4: finalize. W = exp(L - max)*inv (in place), ctx = sum_b W * FV.
// ===========================================================================
__global__ __launch_bounds__(256) void finalize_kernel(
    float* __restrict__ W, const float* __restrict__ FV, float* __restrict__ ctx)
{
    const int i = blockIdx.x;
    const int t = threadIdx.x;
    __shared__ float smax[256];
    __shared__ float sinv[256];
    smax[t] = g_rowmax[i * BB + t];
    sinv[t] = g_rowinv[i * BB + t];
    __syncthreads();

    const size_t base = (size_t)i * BB * DD + (size_t)t * 4;
    float cx = 0.f, cy = 0.f, cz = 0.f, cw = 0.f;

    #pragma unroll 4
    for (int b = 0; b < BB; ++b) {
        const size_t off = base + (size_t)b * DD;
        float4 l = *(const float4*)(W + off);
        float4 f = *(const float4*)(FV + off);
        const float m = smax[b], iv = sinv[b];
        float4 w;
        w.x = __expf(l.x - m) * iv;
        w.y = __expf(l.y - m) * iv;
        w.z = __expf(l.z - m) * iv;
        w.w = __expf(l.w - m) * iv;
        *(float4*)(W + off) = w;
        cx = fmaf(w.x, f.x, cx);
        cy = fmaf(w.y, f.y, cy);
        cz = fmaf(w.z, f.z, cz);
        cw = fmaf(w.w, f.w, cw);
    }
    float4 o = {cx, cy, cz, cw};
    *(float4*)(ctx + (size_t)i * DD + (size_t)t * 4) = o;
}

// ===========================================================================
// launch
// ===========================================================================
extern "C" void kernel_launch(void* const* d_in, const int* in_sizes, int n_in,
                              void* d_out, int out_size)
{
    (void)in_sizes; (void)n_in; (void)out_size;
    const float* FV    = (const float*)d_in[0];  // [256,256,1024]
    const float* state = (const float*)d_in[1];  // [256,1024]
    const float* Q     = (const float*)d_in[2];  // [1024,1024]
    const float* Kmat  = (const float*)d_in[3];  // [1024,256]

    float* ctx = (float*)d_out;                      // [256,1024]
    float* W   = (float*)d_out + (size_t)BB * DD;    // [256,256,1024]

    cudaFuncSetAttribute(logits_mma, cudaFuncAttributeMaxDynamicSharedMemorySize,
                         LOGITS_SMEM);

    gemm_state_qt<<<dim3(SS / 64, BB / 64), 256>>>(state, Q);
    gemm_a_k     <<<dim3(NN / 64, BB / 64), 256>>>(Kmat);
    convert_m    <<<BB * NN / 256, 256>>>();
    convert_fv   <<<(int)(((size_t)BB * NN * DD) / 4 / 256), 256>>>(FV);
    logits_mma   <<<dim3(DD / 128, BB / 128, BB), 256, LOGITS_SMEM>>>(W);
    merge_stats  <<<(BB * BB) / 256, 256>>>();
    finalize_kernel<<<BB, 256>>>(W, FV, ctx);
}